// round 1
// baseline (speedup 1.0000x reference)
#include <cuda_runtime.h>
#include <cstdint>

// Problem shape (fixed by the dataset)
#define BSZ 2
#define SEQ 2048
#define HID 1024
#define NS  4      // s (sqrt_n_heads)
#define H   256    // head size

// GEMM tiling
#define BM 128
#define BN 128
#define BK 16
#define THREADS 256

// Scratch (device globals — no allocation allowed in kernel_launch)
__device__ float g_K  [BSZ*NS*H*H];                 // [b][q][f][g]  Gram matrices
__device__ float g_tmp[(size_t)BSZ*NS*H*NS*H];      // [b][a][e][q*H+g]
__device__ float g_M  [BSZ*NS*H*H];                 // [b][a][e][g'] folded operator

// Generic fp32 tiled GEMM block: C[m0:m0+128, n0:n0+128] (+)= A(^T) * B over k in [kBegin,kEnd)
// TRANS_A: A is [K x M] row-major (used for Gram X^T X). Otherwise A is [M x K].
// B is always [K x N] row-major.
template<bool TRANS_A, bool ATOMIC>
__device__ __forceinline__ void gemm_core(
    const float* __restrict__ A, int lda,
    const float* __restrict__ B, int ldb,
    float* __restrict__ C, int ldc,
    int m0, int n0, int kBegin, int kEnd)
{
    __shared__ float As[BK][BM + 4];
    __shared__ float Bs[BK][BN + 4];

    const int tid = threadIdx.x;
    const int tr  = tid >> 4;     // 0..15 : row group (8 rows each)
    const int tc  = tid & 15;     // 0..15 : col group (8 cols each)

    float acc[8][8];
    #pragma unroll
    for (int i = 0; i < 8; ++i)
        #pragma unroll
        for (int j = 0; j < 8; ++j) acc[i][j] = 0.f;

    const float* Bb = B + n0;

    for (int k0 = kBegin; k0 < kEnd; k0 += BK) {
        // ---- load A tile into As[kk][mm] ----
        if (TRANS_A) {
            const float* Ab = A + m0;  // column offset
            #pragma unroll
            for (int l = 0; l < 2; ++l) {
                int idx = tid + l * THREADS;          // 0..511 float4 slots
                int kk  = idx >> 5;                   // /32
                int mm  = (idx & 31) << 2;
                float4 v = *reinterpret_cast<const float4*>(Ab + (size_t)(k0 + kk) * lda + mm);
                *reinterpret_cast<float4*>(&As[kk][mm]) = v;
            }
        } else {
            const float* Ab = A + (size_t)m0 * lda;
            #pragma unroll
            for (int l = 0; l < 2; ++l) {
                int idx = tid + l * THREADS;
                int mm  = idx >> 2;                   // 0..127
                int kk4 = (idx & 3) << 2;             // 0,4,8,12
                float4 v = *reinterpret_cast<const float4*>(Ab + (size_t)mm * lda + k0 + kk4);
                As[kk4 + 0][mm] = v.x;
                As[kk4 + 1][mm] = v.y;
                As[kk4 + 2][mm] = v.z;
                As[kk4 + 3][mm] = v.w;
            }
        }
        // ---- load B tile ----
        #pragma unroll
        for (int l = 0; l < 2; ++l) {
            int idx = tid + l * THREADS;
            int kk  = idx >> 5;
            int nn  = (idx & 31) << 2;
            float4 v = *reinterpret_cast<const float4*>(Bb + (size_t)(k0 + kk) * ldb + nn);
            *reinterpret_cast<float4*>(&Bs[kk][nn]) = v;
        }
        __syncthreads();

        #pragma unroll
        for (int kk = 0; kk < BK; ++kk) {
            float a[8], b[8];
            *reinterpret_cast<float4*>(a)     = *reinterpret_cast<const float4*>(&As[kk][tr * 8]);
            *reinterpret_cast<float4*>(a + 4) = *reinterpret_cast<const float4*>(&As[kk][tr * 8 + 4]);
            *reinterpret_cast<float4*>(b)     = *reinterpret_cast<const float4*>(&Bs[kk][tc * 8]);
            *reinterpret_cast<float4*>(b + 4) = *reinterpret_cast<const float4*>(&Bs[kk][tc * 8 + 4]);
            #pragma unroll
            for (int i = 0; i < 8; ++i)
                #pragma unroll
                for (int j = 0; j < 8; ++j)
                    acc[i][j] = fmaf(a[i], b[j], acc[i][j]);
        }
        __syncthreads();
    }

    if (ATOMIC) {
        #pragma unroll
        for (int i = 0; i < 8; ++i) {
            int r = m0 + tr * 8 + i;
            #pragma unroll
            for (int j = 0; j < 8; ++j)
                atomicAdd(&C[(size_t)r * ldc + n0 + tc * 8 + j], acc[i][j]);
        }
    } else {
        #pragma unroll
        for (int i = 0; i < 8; ++i) {
            int r = m0 + tr * 8 + i;
            *reinterpret_cast<float4*>(&C[(size_t)r * ldc + n0 + tc * 8])     = *reinterpret_cast<float4*>(&acc[i][0]);
            *reinterpret_cast<float4*>(&C[(size_t)r * ldc + n0 + tc * 8 + 4]) = *reinterpret_cast<float4*>(&acc[i][4]);
        }
    }
}

// Zero the split-K accumulation targets (g_K, g_M)
__global__ void __launch_bounds__(THREADS) k_zero() {
    const size_t n = (size_t)BSZ * NS * H * H;
    size_t idx    = (size_t)blockIdx.x * blockDim.x + threadIdx.x;
    size_t stride = (size_t)gridDim.x * blockDim.x;
    for (size_t i = idx; i < n; i += stride) { g_K[i] = 0.f; g_M[i] = 0.f; }
}

// Pass 1: K[b,q] = X_q^T X_q,  X_q = hidden[b, :, q*H:(q+1)*H]  (split-K over t, 8 chunks of 256)
__global__ void __launch_bounds__(THREADS) k_gram(const float* __restrict__ hidden) {
    int z = blockIdx.z;           // pair*8 + split
    int pair = z >> 3, split = z & 7;
    int b = pair >> 2, q = pair & 3;
    const float* A = hidden + (size_t)b * SEQ * HID + q * H;   // [t, f], lda = HID
    gemm_core<true, true>(A, HID, A, HID,
                          g_K + (size_t)pair * H * H, H,
                          blockIdx.x * BM, blockIdx.y * BN,
                          split * 256, split * 256 + 256);
}

// Pass 2: tmp[b,a][e, q*H+g] = queries[a, e, q*H+f] * K[b,q][f,g]   (32 GEMMs 256^3)
__global__ void __launch_bounds__(THREADS) k_proj(const float* __restrict__ queries) {
    int g = blockIdx.z;                         // 0..31 : ((b*4+a)*4+q)
    int b = g >> 4, a = (g >> 2) & 3, q = g & 3;
    const float* A = queries + (size_t)a * H * HID + q * H;    // [e, f], lda = HID
    const float* B = g_K + (size_t)((b << 2) | q) * H * H;     // [f, g], ldb = H
    float* C = g_tmp + (size_t)((b << 2) | a) * H * (NS * H) + q * H;
    gemm_core<false, false>(A, HID, B, H, C, NS * H,
                            blockIdx.x * BM, blockIdx.y * BN, 0, H);
}

// Pass 3: M[b,a] = tmp[b,a] [256x1024] @ combiners[a] [1024x256]   (split-K, 4 chunks of 256)
__global__ void __launch_bounds__(THREADS) k_comb(const float* __restrict__ combiners) {
    int z = blockIdx.z;            // pair*4 + split
    int pair = z >> 2, split = z & 3;
    int a = pair & 3;
    const float* A = g_tmp + (size_t)pair * H * (NS * H);      // lda = 1024
    const float* B = combiners + (size_t)a * (NS * H) * H;     // ldb = H
    float* C = g_M + (size_t)pair * H * H;
    gemm_core<false, true>(A, NS * H, B, H, C, H,
                           blockIdx.x * BM, blockIdx.y * BN,
                           split * 256, split * 256 + 256);
}

// Pass 4: out[b, :, a*H:(a+1)*H] = hidden[b, :, a*H:(a+1)*H] @ M[b,a]
__global__ void __launch_bounds__(THREADS) k_out(const float* __restrict__ hidden,
                                                 float* __restrict__ out) {
    int pair = blockIdx.z;
    int b = pair >> 2, a = pair & 3;
    const float* A = hidden + (size_t)b * SEQ * HID + a * H;   // lda = HID
    const float* B = g_M + (size_t)pair * H * H;               // ldb = H
    float* C = out + (size_t)b * SEQ * HID + a * H;            // ldc = HID
    gemm_core<false, false>(A, HID, B, H, C, HID,
                            blockIdx.x * BM, blockIdx.y * BN, 0, H);
}

extern "C" void kernel_launch(void* const* d_in, const int* in_sizes, int n_in,
                              void* d_out, int out_size) {
    const float* hidden    = (const float*)d_in[0];  // [2, 2048, 1024]
    const float* queries   = (const float*)d_in[1];  // [4, 256, 1024]
    const float* combiners = (const float*)d_in[2];  // [4, 1024, 256]
    float* out = (float*)d_out;                      // [2, 2048, 1024]

    k_zero<<<512, THREADS>>>();
    k_gram<<<dim3(2, 2, 64), THREADS>>>(hidden);     // 256 blocks
    k_proj<<<dim3(2, 2, 32), THREADS>>>(queries);    // 128 blocks
    k_comb<<<dim3(2, 2, 32), THREADS>>>(combiners);  // 128 blocks
    k_out <<<dim3(16, 2, 8), THREADS>>>(hidden, out);// 256 blocks
}

// round 2
// speedup vs baseline: 1.0006x; 1.0006x over previous
#include <cuda_runtime.h>
#include <cstdint>

// Problem shape (fixed by the dataset)
#define BSZ 2
#define SEQ 2048
#define HID 1024
#define NS  4      // s (sqrt_n_heads)
#define H   256    // head size

// GEMM tiling
#define BM 128
#define BN 128
#define BK 16
#define THREADS 256

// Scratch (device globals — no allocation allowed in kernel_launch)
__device__ float g_K  [BSZ*NS*H*H];                 // [b][q][f][g]  Gram matrices
__device__ float g_tmp[(size_t)BSZ*NS*H*NS*H];      // [b][a][e][q*H+g]
__device__ float g_M  [BSZ*NS*H*H];                 // [b][a][e][g'] folded operator

// Generic fp32 tiled GEMM block: C[m0:m0+128, n0:n0+128] (+)= A(^T) * B over k in [kBegin,kEnd)
// TRANS_A: A is [K x M] row-major (used for Gram X^T X). Otherwise A is [M x K].
// B is always [K x N] row-major.
template<bool TRANS_A, bool ATOMIC>
__device__ __forceinline__ void gemm_core(
    const float* __restrict__ A, int lda,
    const float* __restrict__ B, int ldb,
    float* __restrict__ C, int ldc,
    int m0, int n0, int kBegin, int kEnd)
{
    __shared__ float As[BK][BM + 4];
    __shared__ float Bs[BK][BN + 4];

    const int tid = threadIdx.x;
    const int tr  = tid >> 4;     // 0..15 : row group (8 rows each)
    const int tc  = tid & 15;     // 0..15 : col group (8 cols each)

    float acc[8][8];
    #pragma unroll
    for (int i = 0; i < 8; ++i)
        #pragma unroll
        for (int j = 0; j < 8; ++j) acc[i][j] = 0.f;

    const float* Bb = B + n0;

    for (int k0 = kBegin; k0 < kEnd; k0 += BK) {
        // ---- load A tile into As[kk][mm] ----
        if (TRANS_A) {
            const float* Ab = A + m0;  // column offset
            #pragma unroll
            for (int l = 0; l < 2; ++l) {
                int idx = tid + l * THREADS;          // 0..511 float4 slots
                int kk  = idx >> 5;                   // /32
                int mm  = (idx & 31) << 2;
                float4 v = *reinterpret_cast<const float4*>(Ab + (size_t)(k0 + kk) * lda + mm);
                *reinterpret_cast<float4*>(&As[kk][mm]) = v;
            }
        } else {
            const float* Ab = A + (size_t)m0 * lda;
            #pragma unroll
            for (int l = 0; l < 2; ++l) {
                int idx = tid + l * THREADS;
                int mm  = idx >> 2;                   // 0..127
                int kk4 = (idx & 3) << 2;             // 0,4,8,12
                float4 v = *reinterpret_cast<const float4*>(Ab + (size_t)mm * lda + k0 + kk4);
                As[kk4 + 0][mm] = v.x;
                As[kk4 + 1][mm] = v.y;
                As[kk4 + 2][mm] = v.z;
                As[kk4 + 3][mm] = v.w;
            }
        }
        // ---- load B tile ----
        #pragma unroll
        for (int l = 0; l < 2; ++l) {
            int idx = tid + l * THREADS;
            int kk  = idx >> 5;
            int nn  = (idx & 31) << 2;
            float4 v = *reinterpret_cast<const float4*>(Bb + (size_t)(k0 + kk) * ldb + nn);
            *reinterpret_cast<float4*>(&Bs[kk][nn]) = v;
        }
        __syncthreads();

        #pragma unroll
        for (int kk = 0; kk < BK; ++kk) {
            float a[8], b[8];
            *reinterpret_cast<float4*>(a)     = *reinterpret_cast<const float4*>(&As[kk][tr * 8]);
            *reinterpret_cast<float4*>(a + 4) = *reinterpret_cast<const float4*>(&As[kk][tr * 8 + 4]);
            *reinterpret_cast<float4*>(b)     = *reinterpret_cast<const float4*>(&Bs[kk][tc * 8]);
            *reinterpret_cast<float4*>(b + 4) = *reinterpret_cast<const float4*>(&Bs[kk][tc * 8 + 4]);
            #pragma unroll
            for (int i = 0; i < 8; ++i)
                #pragma unroll
                for (int j = 0; j < 8; ++j)
                    acc[i][j] = fmaf(a[i], b[j], acc[i][j]);
        }
        __syncthreads();
    }

    if (ATOMIC) {
        #pragma unroll
        for (int i = 0; i < 8; ++i) {
            int r = m0 + tr * 8 + i;
            #pragma unroll
            for (int j = 0; j < 8; ++j)
                atomicAdd(&C[(size_t)r * ldc + n0 + tc * 8 + j], acc[i][j]);
        }
    } else {
        #pragma unroll
        for (int i = 0; i < 8; ++i) {
            int r = m0 + tr * 8 + i;
            *reinterpret_cast<float4*>(&C[(size_t)r * ldc + n0 + tc * 8])     = *reinterpret_cast<float4*>(&acc[i][0]);
            *reinterpret_cast<float4*>(&C[(size_t)r * ldc + n0 + tc * 8 + 4]) = *reinterpret_cast<float4*>(&acc[i][4]);
        }
    }
}

// Zero the split-K accumulation targets (g_K, g_M)
__global__ void __launch_bounds__(THREADS) k_zero() {
    const size_t n = (size_t)BSZ * NS * H * H;
    size_t idx    = (size_t)blockIdx.x * blockDim.x + threadIdx.x;
    size_t stride = (size_t)gridDim.x * blockDim.x;
    for (size_t i = idx; i < n; i += stride) { g_K[i] = 0.f; g_M[i] = 0.f; }
}

// Pass 1: K[b,q] = X_q^T X_q,  X_q = hidden[b, :, q*H:(q+1)*H]  (split-K over t, 8 chunks of 256)
__global__ void __launch_bounds__(THREADS) k_gram(const float* __restrict__ hidden) {
    int z = blockIdx.z;           // pair*8 + split
    int pair = z >> 3, split = z & 7;
    int b = pair >> 2, q = pair & 3;
    const float* A = hidden + (size_t)b * SEQ * HID + q * H;   // [t, f], lda = HID
    gemm_core<true, true>(A, HID, A, HID,
                          g_K + (size_t)pair * H * H, H,
                          blockIdx.x * BM, blockIdx.y * BN,
                          split * 256, split * 256 + 256);
}

// Pass 2: tmp[b,a][e, q*H+g] = queries[a, e, q*H+f] * K[b,q][f,g]   (32 GEMMs 256^3)
__global__ void __launch_bounds__(THREADS) k_proj(const float* __restrict__ queries) {
    int g = blockIdx.z;                         // 0..31 : ((b*4+a)*4+q)
    int b = g >> 4, a = (g >> 2) & 3, q = g & 3;
    const float* A = queries + (size_t)a * H * HID + q * H;    // [e, f], lda = HID
    const float* B = g_K + (size_t)((b << 2) | q) * H * H;     // [f, g], ldb = H
    float* C = g_tmp + (size_t)((b << 2) | a) * H * (NS * H) + q * H;
    gemm_core<false, false>(A, HID, B, H, C, NS * H,
                            blockIdx.x * BM, blockIdx.y * BN, 0, H);
}

// Pass 3: M[b,a] = tmp[b,a] [256x1024] @ combiners[a] [1024x256]   (split-K, 4 chunks of 256)
__global__ void __launch_bounds__(THREADS) k_comb(const float* __restrict__ combiners) {
    int z = blockIdx.z;            // pair*4 + split
    int pair = z >> 2, split = z & 3;
    int a = pair & 3;
    const float* A = g_tmp + (size_t)pair * H * (NS * H);      // lda = 1024
    const float* B = combiners + (size_t)a * (NS * H) * H;     // ldb = H
    float* C = g_M + (size_t)pair * H * H;
    gemm_core<false, true>(A, NS * H, B, H, C, H,
                           blockIdx.x * BM, blockIdx.y * BN,
                           split * 256, split * 256 + 256);
}

// Pass 4: out[b, :, a*H:(a+1)*H] = hidden[b, :, a*H:(a+1)*H] @ M[b,a]
__global__ void __launch_bounds__(THREADS) k_out(const float* __restrict__ hidden,
                                                 float* __restrict__ out) {
    int pair = blockIdx.z;
    int b = pair >> 2, a = pair & 3;
    const float* A = hidden + (size_t)b * SEQ * HID + a * H;   // lda = HID
    const float* B = g_M + (size_t)pair * H * H;               // ldb = H
    float* C = out + (size_t)b * SEQ * HID + a * H;            // ldc = HID
    gemm_core<false, false>(A, HID, B, H, C, HID,
                            blockIdx.x * BM, blockIdx.y * BN, 0, H);
}

extern "C" void kernel_launch(void* const* d_in, const int* in_sizes, int n_in,
                              void* d_out, int out_size) {
    const float* hidden    = (const float*)d_in[0];  // [2, 2048, 1024]
    const float* queries   = (const float*)d_in[1];  // [4, 256, 1024]
    const float* combiners = (const float*)d_in[2];  // [4, 1024, 256]
    float* out = (float*)d_out;                      // [2, 2048, 1024]

    k_zero<<<512, THREADS>>>();
    k_gram<<<dim3(2, 2, 64), THREADS>>>(hidden);     // 256 blocks
    k_proj<<<dim3(2, 2, 32), THREADS>>>(queries);    // 128 blocks
    k_comb<<<dim3(2, 2, 32), THREADS>>>(combiners);  // 128 blocks
    k_out <<<dim3(16, 2, 8), THREADS>>>(hidden, out);// 256 blocks
}

// round 4
// speedup vs baseline: 1.9062x; 1.9050x over previous
#include <cuda_runtime.h>
#include <cuda_bf16.h>
#include <cstdint>

using bf16 = __nv_bfloat16;

#define BSZ 2
#define SEQ 2048
#define HID 1024
#define NS  4
#define H   256

// ---------------- device scratch ----------------
__device__ __align__(256) bf16 g_hidH [BSZ*SEQ*HID];
__device__ __align__(256) bf16 g_hidL [BSZ*SEQ*HID];
__device__ __align__(256) bf16 g_hidTH[BSZ*HID*SEQ];
__device__ __align__(256) bf16 g_hidTL[BSZ*HID*SEQ];
__device__ __align__(256) bf16 g_qH   [NS*H*HID];
__device__ __align__(256) bf16 g_qL   [NS*H*HID];
__device__ __align__(256) bf16 g_cTH  [NS*H*HID];
__device__ __align__(256) bf16 g_cTL  [NS*H*HID];
__device__ __align__(256) float g_Kf  [8*H*H];
__device__ __align__(256) bf16 g_KH   [8*H*H];
__device__ __align__(256) bf16 g_KL   [8*H*H];
__device__ __align__(256) bf16 g_tmpH [8*H*HID];
__device__ __align__(256) bf16 g_tmpL [8*H*HID];
__device__ __align__(256) float g_Mf  [8*H*H];      // holds M^T
__device__ __align__(256) bf16 g_MH   [8*H*H];
__device__ __align__(256) bf16 g_ML   [8*H*H];

// ---------------- helpers ----------------
__device__ __forceinline__ void split2(float v, bf16& h, bf16& l) {
    h = __float2bfloat16_rn(v);
    l = __float2bfloat16_rn(v - __bfloat162float(h));
}
__device__ __forceinline__ uint32_t smem_u32(const void* p) {
    uint32_t a;
    asm("{ .reg .u64 t; cvta.to.shared.u64 t, %1; cvt.u32.u64 %0, t; }" : "=r"(a) : "l"(p));
    return a;
}
__device__ __forceinline__ void cpa(uint32_t dst, const void* src) {
    asm volatile("cp.async.ca.shared.global [%0], [%1], 16;" :: "r"(dst), "l"(src));
}
__device__ __forceinline__ void ldsm4(uint32_t (&r)[4], uint32_t addr) {
    asm volatile("ldmatrix.sync.aligned.m8n8.x4.shared.b16 {%0,%1,%2,%3}, [%4];"
        : "=r"(r[0]), "=r"(r[1]), "=r"(r[2]), "=r"(r[3]) : "r"(addr));
}
__device__ __forceinline__ void mma16816(float (&d)[4], const uint32_t (&a)[4],
                                         uint32_t b0, uint32_t b1) {
    asm volatile("mma.sync.aligned.m16n8k16.row.col.f32.bf16.bf16.f32 "
        "{%0,%1,%2,%3}, {%4,%5,%6,%7}, {%8,%9}, {%0,%1,%2,%3};"
        : "+f"(d[0]), "+f"(d[1]), "+f"(d[2]), "+f"(d[3])
        : "r"(a[0]), "r"(a[1]), "r"(a[2]), "r"(a[3]), "r"(b0), "r"(b1));
}
__device__ __forceinline__ uint32_t swz(int row, int c) {
    return (uint32_t)(row * 64 + ((c ^ ((row >> 1) & 3)) << 4));
}

#define SM_STAGE 32768
#define SM_BYTES 65536

// Load one [128 x 32]bf16 tile x4 (AH, AL, BH, BL) into stage sb
__device__ __forceinline__ void load_stage(uint32_t sb,
        const bf16* __restrict__ AH, const bf16* __restrict__ AL, int lda,
        const bf16* __restrict__ BH, const bf16* __restrict__ BL, int ldb, int k0) {
    int tid = threadIdx.x;
    #pragma unroll
    for (int t = 0; t < 2; ++t) {
        int cid = tid + t * 256;
        int row = cid >> 2, c = cid & 3;
        uint32_t so = swz(row, c);
        size_t oa = (size_t)row * lda + k0 + c * 8;
        size_t ob = (size_t)row * ldb + k0 + c * 8;
        cpa(sb + so,         AH + oa);
        cpa(sb + 8192 + so,  AL + oa);
        cpa(sb + 16384 + so, BH + ob);
        cpa(sb + 24576 + so, BL + ob);
    }
    asm volatile("cp.async.commit_group;" ::: "memory");
}

// C[128,128] = A[128,K] * B[128,K]^T  (split bf16, 3 MMAs)
// EPI: 0 = atomicAdd fp32, 1 = store fp32, 2 = split-store bf16 H/L
template<int EPI>
__device__ void gemm_mma(const bf16* AH, const bf16* AL, int lda,
                         const bf16* BH, const bf16* BL, int ldb, int kIters,
                         float* Cf, bf16* CH, bf16* CL, int ldc) {
    extern __shared__ char smem[];
    const uint32_t sbase = smem_u32(smem);
    const int tid = threadIdx.x, lane = tid & 31, wid = tid >> 5;
    const int wm = wid & 1, wn = wid >> 1;

    float acc[4][4][4];
    #pragma unroll
    for (int i = 0; i < 4; ++i)
        #pragma unroll
        for (int j = 0; j < 4; ++j)
            #pragma unroll
            for (int v = 0; v < 4; ++v) acc[i][j][v] = 0.f;

    load_stage(sbase, AH, AL, lda, BH, BL, ldb, 0);

    const int mi = lane >> 3, lr = lane & 7;
    const int rA0 = wm * 64 + (mi & 1) * 8 + lr;
    const int rB0 = wn * 32 + (mi & 1) * 8 + lr;
    const int chb = mi >> 1;

    for (int it = 0; it < kIters; ++it) {
        uint32_t sb = sbase + (uint32_t)(it & 1) * SM_STAGE;
        if (it + 1 < kIters) {
            load_stage(sbase + (uint32_t)((it + 1) & 1) * SM_STAGE,
                       AH, AL, lda, BH, BL, ldb, (it + 1) * 32);
            asm volatile("cp.async.wait_group 1;" ::: "memory");
        } else {
            asm volatile("cp.async.wait_group 0;" ::: "memory");
        }
        __syncthreads();

        #pragma unroll
        for (int kk = 0; kk < 2; ++kk) {
            int c = kk * 2 + chb;
            uint32_t ah[4][4], al[4][4], bh[2][4], bl[2][4];
            #pragma unroll
            for (int i = 0; i < 4; ++i) {
                int r = rA0 + i * 16;
                uint32_t so = swz(r, c);
                ldsm4(ah[i], sb + so);
                ldsm4(al[i], sb + 8192 + so);
            }
            #pragma unroll
            for (int j = 0; j < 2; ++j) {
                int r = rB0 + j * 16;
                uint32_t so = swz(r, c);
                ldsm4(bh[j], sb + 16384 + so);
                ldsm4(bl[j], sb + 24576 + so);
            }
            #pragma unroll
            for (int i = 0; i < 4; ++i)
                #pragma unroll
                for (int j = 0; j < 4; ++j) {
                    int j2 = j >> 1, jo = j & 1;
                    mma16816(acc[i][j], ah[i], bh[j2][jo], bh[j2][jo + 2]);
                    mma16816(acc[i][j], ah[i], bl[j2][jo], bl[j2][jo + 2]);
                    mma16816(acc[i][j], al[i], bh[j2][jo], bh[j2][jo + 2]);
                }
        }
        __syncthreads();
    }

    #pragma unroll
    for (int i = 0; i < 4; ++i)
        #pragma unroll
        for (int j = 0; j < 4; ++j) {
            int r   = wm * 64 + i * 16 + (lane >> 2);
            int col = wn * 32 + j * 8 + (lane & 3) * 2;
            if (EPI == 0) {
                atomicAdd(Cf + (size_t)r * ldc + col,           acc[i][j][0]);
                atomicAdd(Cf + (size_t)r * ldc + col + 1,       acc[i][j][1]);
                atomicAdd(Cf + (size_t)(r + 8) * ldc + col,     acc[i][j][2]);
                atomicAdd(Cf + (size_t)(r + 8) * ldc + col + 1, acc[i][j][3]);
            } else if (EPI == 1) {
                *reinterpret_cast<float2*>(Cf + (size_t)r * ldc + col) =
                    make_float2(acc[i][j][0], acc[i][j][1]);
                *reinterpret_cast<float2*>(Cf + (size_t)(r + 8) * ldc + col) =
                    make_float2(acc[i][j][2], acc[i][j][3]);
            } else {
                bf16 h0, l0, h1, l1;
                __nv_bfloat162 ph, pl;
                split2(acc[i][j][0], h0, l0); split2(acc[i][j][1], h1, l1);
                ph.x = h0; ph.y = h1; pl.x = l0; pl.y = l1;
                *reinterpret_cast<__nv_bfloat162*>(CH + (size_t)r * ldc + col) = ph;
                *reinterpret_cast<__nv_bfloat162*>(CL + (size_t)r * ldc + col) = pl;
                split2(acc[i][j][2], h0, l0); split2(acc[i][j][3], h1, l1);
                ph.x = h0; ph.y = h1; pl.x = l0; pl.y = l1;
                *reinterpret_cast<__nv_bfloat162*>(CH + (size_t)(r + 8) * ldc + col) = ph;
                *reinterpret_cast<__nv_bfloat162*>(CL + (size_t)(r + 8) * ldc + col) = pl;
            }
        }
}

// ---- pass wrappers ----
__global__ void __launch_bounds__(256) k_p1() {          // Gram: K = hidT * hidT^T, split-K
    int z = blockIdx.z, pair = z >> 3, split = z & 7;
    int b = pair >> 2, q = pair & 3;
    size_t base = ((size_t)b * HID + q * H) * SEQ + split * 256;
    int m0 = blockIdx.x * 128, n0 = blockIdx.y * 128;
    gemm_mma<0>(g_hidTH + base + (size_t)m0 * SEQ, g_hidTL + base + (size_t)m0 * SEQ, SEQ,
                g_hidTH + base + (size_t)n0 * SEQ, g_hidTL + base + (size_t)n0 * SEQ, SEQ,
                8, g_Kf + (size_t)pair * H * H + m0 * H + n0, nullptr, nullptr, H);
}
__global__ void __launch_bounds__(256) k_p2() {          // tmp = qw * K (K symmetric)
    int z = blockIdx.z, b = z >> 4, a = (z >> 2) & 3, q = z & 3;
    int m0 = blockIdx.x * 128, n0 = blockIdx.y * 128;
    size_t ab = (size_t)a * H * HID + (size_t)m0 * HID + q * H;
    size_t bb = (size_t)((b << 2) | q) * H * H + (size_t)n0 * H;
    size_t cb = (size_t)((b << 2) | a) * H * HID + (size_t)m0 * HID + q * H + n0;
    gemm_mma<2>(g_qH + ab, g_qL + ab, HID, g_KH + bb, g_KL + bb, H,
                8, nullptr, g_tmpH + cb, g_tmpL + cb, HID);
}
__global__ void __launch_bounds__(256) k_p3() {          // M^T = cT * tmp^T, split-K
    int z = blockIdx.z, pair = z >> 2, split = z & 3;
    int a = pair & 3;
    int m0 = blockIdx.x * 128, n0 = blockIdx.y * 128;
    size_t ab = (size_t)a * H * HID + (size_t)m0 * HID + split * 256;
    size_t bb = (size_t)pair * H * HID + (size_t)n0 * HID + split * 256;
    gemm_mma<0>(g_cTH + ab, g_cTL + ab, HID, g_tmpH + bb, g_tmpL + bb, HID,
                8, g_Mf + (size_t)pair * H * H + m0 * H + n0, nullptr, nullptr, H);
}
__global__ void __launch_bounds__(256) k_p4(float* __restrict__ out) {  // out = hid * M
    int pair = blockIdx.z, b = pair >> 2, a = pair & 3;
    int m0 = blockIdx.x * 128, n0 = blockIdx.y * 128;
    size_t ab = (size_t)b * SEQ * HID + (size_t)m0 * HID + a * H;
    size_t bb = (size_t)pair * H * H + (size_t)n0 * H;
    gemm_mma<1>(g_hidH + ab, g_hidL + ab, HID, g_MH + bb, g_ML + bb, H,
                8, out + ab + n0, nullptr, nullptr, HID);
}

// ---- prep kernels ----
__global__ void __launch_bounds__(256) k_prep_hidden(const float* __restrict__ hid) {
    __shared__ bf16 shH[32][33], shL[32][33];
    int x = blockIdx.x;
    int b = x >> 11, tt = (x >> 5) & 63, ft = x & 31;
    int tx = threadIdx.x & 31, ty = threadIdx.x >> 5;
    int t0 = tt * 32, f0 = ft * 32;
    #pragma unroll
    for (int i = 0; i < 4; ++i) {
        int r = ty + i * 8;
        size_t idx = ((size_t)b * SEQ + t0 + r) * HID + f0 + tx;
        float v = hid[idx];
        bf16 h, l; split2(v, h, l);
        g_hidH[idx] = h; g_hidL[idx] = l;
        shH[r][tx] = h; shL[r][tx] = l;
    }
    __syncthreads();
    #pragma unroll
    for (int i = 0; i < 4; ++i) {
        int r = ty + i * 8;
        size_t idx = ((size_t)b * HID + f0 + r) * SEQ + t0 + tx;
        g_hidTH[idx] = shH[tx][r];
        g_hidTL[idx] = shL[tx][r];
    }
}
__global__ void __launch_bounds__(256) k_prep_small(const float* __restrict__ q,
                                                    const float* __restrict__ c) {
    int blk = blockIdx.x, tid = threadIdx.x;
    if (blk < 1024) {                       // split queries
        size_t i = (size_t)blk * 1024 + tid * 4;
        float4 v = *reinterpret_cast<const float4*>(q + i);
        bf16 h, l;
        split2(v.x, h, l); g_qH[i] = h;   g_qL[i] = l;
        split2(v.y, h, l); g_qH[i+1] = h; g_qL[i+1] = l;
        split2(v.z, h, l); g_qH[i+2] = h; g_qL[i+2] = l;
        split2(v.w, h, l); g_qH[i+3] = h; g_qL[i+3] = l;
    } else if (blk < 2048) {                // transpose + split combiners
        __shared__ bf16 shH[32][33], shL[32][33];
        int z = blk - 1024;
        int a = z >> 8, kt = (z >> 3) & 31, gt = z & 7;
        int tx = tid & 31, ty = tid >> 5;
        int k0 = kt * 32, g0 = gt * 32;
        #pragma unroll
        for (int i = 0; i < 4; ++i) {
            int r = ty + i * 8;
            float v = c[((size_t)a * HID + k0 + r) * H + g0 + tx];
            bf16 h, l; split2(v, h, l);
            shH[r][tx] = h; shL[r][tx] = l;
        }
        __syncthreads();
        #pragma unroll
        for (int i = 0; i < 4; ++i) {
            int r = ty + i * 8;
            size_t idx = ((size_t)a * H + g0 + r) * HID + k0 + tx;
            g_cTH[idx] = shH[tx][r];
            g_cTL[idx] = shL[tx][r];
        }
    } else {                                // zero g_Kf / g_Mf
        int z = blk - 2048;
        size_t base = (size_t)z * 4096 + tid * 16;
        float* dst = (base < (size_t)8 * H * H) ? g_Kf : (g_Mf - (size_t)8 * H * H);
        float4 zv = make_float4(0.f, 0.f, 0.f, 0.f);
        #pragma unroll
        for (int i = 0; i < 4; ++i)
            *reinterpret_cast<float4*>(dst + base + i * 4) = zv;
    }
}
__global__ void __launch_bounds__(256) k_splitK() {
    size_t i = (size_t)blockIdx.x * 2048 + threadIdx.x * 8;
    #pragma unroll
    for (int j = 0; j < 8; ++j) {
        bf16 h, l; split2(g_Kf[i + j], h, l);
        g_KH[i + j] = h; g_KL[i + j] = l;
    }
}
__global__ void __launch_bounds__(256) k_splitM() {
    size_t i = (size_t)blockIdx.x * 2048 + threadIdx.x * 8;
    #pragma unroll
    for (int j = 0; j < 8; ++j) {
        bf16 h, l; split2(g_Mf[i + j], h, l);
        g_MH[i + j] = h; g_ML[i + j] = l;
    }
}

extern "C" void kernel_launch(void* const* d_in, const int* in_sizes, int n_in,
                              void* d_out, int out_size) {
    const float* hidden    = (const float*)d_in[0];
    const float* queries   = (const float*)d_in[1];
    const float* combiners = (const float*)d_in[2];
    float* out = (float*)d_out;

    cudaFuncSetAttribute(k_p1, cudaFuncAttributeMaxDynamicSharedMemorySize, SM_BYTES);
    cudaFuncSetAttribute(k_p2, cudaFuncAttributeMaxDynamicSharedMemorySize, SM_BYTES);
    cudaFuncSetAttribute(k_p3, cudaFuncAttributeMaxDynamicSharedMemorySize, SM_BYTES);
    cudaFuncSetAttribute(k_p4, cudaFuncAttributeMaxDynamicSharedMemorySize, SM_BYTES);

    k_prep_hidden<<<4096, 256>>>(hidden);
    k_prep_small<<<2304, 256>>>(queries, combiners);
    k_p1<<<dim3(2, 2, 64), 256, SM_BYTES>>>();
    k_splitK<<<256, 256>>>();
    k_p2<<<dim3(2, 2, 32), 256, SM_BYTES>>>();
    k_p3<<<dim3(2, 2, 32), 256, SM_BYTES>>>();
    k_splitM<<<256, 256>>>();
    k_p4<<<dim3(16, 2, 8), 256, SM_BYTES>>>(out);
}

// round 5
// speedup vs baseline: 1.9910x; 1.0445x over previous
#include <cuda_runtime.h>
#include <cuda_bf16.h>
#include <cstdint>

using bf16 = __nv_bfloat16;

#define BSZ 2
#define SEQ 2048
#define HID 1024
#define NS  4
#define H   256

// ---------------- device scratch ----------------
__device__ __align__(256) bf16 g_hidH [BSZ*SEQ*HID];
__device__ __align__(256) bf16 g_hidL [BSZ*SEQ*HID];
__device__ __align__(256) bf16 g_hidTH[BSZ*HID*SEQ];
__device__ __align__(256) bf16 g_hidTL[BSZ*HID*SEQ];
__device__ __align__(256) bf16 g_qH   [NS*H*HID];
__device__ __align__(256) bf16 g_qL   [NS*H*HID];
__device__ __align__(256) bf16 g_cTH  [NS*H*HID];
__device__ __align__(256) bf16 g_cTL  [NS*H*HID];
__device__ __align__(256) float g_Pf  [8*H*H];      // Xh^T Xh
__device__ __align__(256) float g_Qf  [8*H*H];      // Xh^T Xl
__device__ __align__(256) bf16 g_KH   [8*H*H];
__device__ __align__(256) bf16 g_KL   [8*H*H];
__device__ __align__(256) bf16 g_tmpH [8*H*HID];
__device__ __align__(256) bf16 g_tmpL [8*H*HID];
__device__ __align__(256) float g_Mf  [8*H*H];      // M^T
__device__ __align__(256) bf16 g_MH   [8*H*H];
__device__ __align__(256) bf16 g_ML   [8*H*H];

// ---------------- helpers ----------------
__device__ __forceinline__ void split2(float v, bf16& h, bf16& l) {
    h = __float2bfloat16_rn(v);
    l = __float2bfloat16_rn(v - __bfloat162float(h));
}
__device__ __forceinline__ uint32_t smem_u32(const void* p) {
    uint32_t a;
    asm("{ .reg .u64 t; cvta.to.shared.u64 t, %1; cvt.u32.u64 %0, t; }" : "=r"(a) : "l"(p));
    return a;
}
__device__ __forceinline__ void cpa(uint32_t dst, const void* src) {
    asm volatile("cp.async.ca.shared.global [%0], [%1], 16;" :: "r"(dst), "l"(src));
}
__device__ __forceinline__ void ldsm4(uint32_t (&r)[4], uint32_t addr) {
    asm volatile("ldmatrix.sync.aligned.m8n8.x4.shared.b16 {%0,%1,%2,%3}, [%4];"
        : "=r"(r[0]), "=r"(r[1]), "=r"(r[2]), "=r"(r[3]) : "r"(addr));
}
__device__ __forceinline__ void mma16816(float (&d)[4], const uint32_t (&a)[4],
                                         uint32_t b0, uint32_t b1) {
    asm volatile("mma.sync.aligned.m16n8k16.row.col.f32.bf16.bf16.f32 "
        "{%0,%1,%2,%3}, {%4,%5,%6,%7}, {%8,%9}, {%0,%1,%2,%3};"
        : "+f"(d[0]), "+f"(d[1]), "+f"(d[2]), "+f"(d[3])
        : "r"(a[0]), "r"(a[1]), "r"(a[2]), "r"(a[3]), "r"(b0), "r"(b1));
}
__device__ __forceinline__ uint32_t swz(int row, int c) {
    return (uint32_t)(row * 64 + ((c ^ ((row >> 1) & 3)) << 4));
}

// Load one [128 x 32]bf16 tile set into stage sb (NPROD=3: AH,AL,BH,BL; NPROD=1: AH,BH)
template<int NPROD>
__device__ __forceinline__ void load_stage(uint32_t sb,
        const bf16* __restrict__ AH, const bf16* __restrict__ AL, int lda,
        const bf16* __restrict__ BH, const bf16* __restrict__ BL, int ldb, int k0) {
    int tid = threadIdx.x;
    #pragma unroll
    for (int t = 0; t < 2; ++t) {
        int cid = tid + t * 256;
        int row = cid >> 2, c = cid & 3;
        uint32_t so = swz(row, c);
        size_t oa = (size_t)row * lda + k0 + c * 8;
        size_t ob = (size_t)row * ldb + k0 + c * 8;
        if (NPROD == 3) {
            cpa(sb + so,         AH + oa);
            cpa(sb + 8192 + so,  AL + oa);
            cpa(sb + 16384 + so, BH + ob);
            cpa(sb + 24576 + so, BL + ob);
        } else {
            cpa(sb + so,        AH + oa);
            cpa(sb + 8192 + so, BH + ob);
        }
    }
    asm volatile("cp.async.commit_group;" ::: "memory");
}

// C[128,128] = A[128,K] * B[128,K]^T.  NPROD=3: split bf16 (AhBh+AhBl+AlBh); NPROD=1: AhBh only.
// EPI: 0 = atomicAdd fp32, 1 = store fp32, 2 = split-store bf16 H/L
template<int EPI, int NPROD>
__device__ void gemm_mma(const bf16* AH, const bf16* AL, int lda,
                         const bf16* BH, const bf16* BL, int ldb, int kIters,
                         float* Cf, bf16* CH, bf16* CL, int ldc) {
    constexpr uint32_t OFF_BH = (NPROD == 3) ? 16384u : 8192u;
    constexpr uint32_t STAGE  = (NPROD == 3) ? 32768u : 16384u;
    extern __shared__ char smem[];
    const uint32_t sbase = smem_u32(smem);
    const int tid = threadIdx.x, lane = tid & 31, wid = tid >> 5;
    const int wm = wid & 1, wn = wid >> 1;

    float acc[4][4][4];
    #pragma unroll
    for (int i = 0; i < 4; ++i)
        #pragma unroll
        for (int j = 0; j < 4; ++j)
            #pragma unroll
            for (int v = 0; v < 4; ++v) acc[i][j][v] = 0.f;

    load_stage<NPROD>(sbase,         AH, AL, lda, BH, BL, ldb, 0);
    load_stage<NPROD>(sbase + STAGE, AH, AL, lda, BH, BL, ldb, 32);

    const int mi = lane >> 3, lr = lane & 7;
    const int rA0 = wm * 64 + (mi & 1) * 8 + lr;
    const int rB0 = wn * 32 + (mi & 1) * 8 + lr;
    const int chb = mi >> 1;

    for (int it = 0; it < kIters; ++it) {
        if (it + 1 < kIters)
            asm volatile("cp.async.wait_group 1;" ::: "memory");
        else
            asm volatile("cp.async.wait_group 0;" ::: "memory");
        __syncthreads();

        uint32_t sb = sbase + (uint32_t)(it % 3) * STAGE;
        if (it + 2 < kIters)
            load_stage<NPROD>(sbase + (uint32_t)((it + 2) % 3) * STAGE,
                              AH, AL, lda, BH, BL, ldb, (it + 2) * 32);

        #pragma unroll
        for (int kk = 0; kk < 2; ++kk) {
            int c = kk * 2 + chb;
            uint32_t ah[4][4], al[4][4], bh[2][4], bl[2][4];
            #pragma unroll
            for (int i = 0; i < 4; ++i) {
                int r = rA0 + i * 16;
                uint32_t so = swz(r, c);
                ldsm4(ah[i], sb + so);
                if (NPROD == 3) ldsm4(al[i], sb + 8192 + so);
            }
            #pragma unroll
            for (int j = 0; j < 2; ++j) {
                int r = rB0 + j * 16;
                uint32_t so = swz(r, c);
                ldsm4(bh[j], sb + OFF_BH + so);
                if (NPROD == 3) ldsm4(bl[j], sb + 24576 + so);
            }
            #pragma unroll
            for (int i = 0; i < 4; ++i)
                #pragma unroll
                for (int j = 0; j < 4; ++j) {
                    int j2 = j >> 1, jo = j & 1;
                    mma16816(acc[i][j], ah[i], bh[j2][jo], bh[j2][jo + 2]);
                    if (NPROD == 3) {
                        mma16816(acc[i][j], ah[i], bl[j2][jo], bl[j2][jo + 2]);
                        mma16816(acc[i][j], al[i], bh[j2][jo], bh[j2][jo + 2]);
                    }
                }
        }
    }

    #pragma unroll
    for (int i = 0; i < 4; ++i)
        #pragma unroll
        for (int j = 0; j < 4; ++j) {
            int r   = wm * 64 + i * 16 + (lane >> 2);
            int col = wn * 32 + j * 8 + (lane & 3) * 2;
            if (EPI == 0) {
                atomicAdd(Cf + (size_t)r * ldc + col,           acc[i][j][0]);
                atomicAdd(Cf + (size_t)r * ldc + col + 1,       acc[i][j][1]);
                atomicAdd(Cf + (size_t)(r + 8) * ldc + col,     acc[i][j][2]);
                atomicAdd(Cf + (size_t)(r + 8) * ldc + col + 1, acc[i][j][3]);
            } else if (EPI == 1) {
                *reinterpret_cast<float2*>(Cf + (size_t)r * ldc + col) =
                    make_float2(acc[i][j][0], acc[i][j][1]);
                *reinterpret_cast<float2*>(Cf + (size_t)(r + 8) * ldc + col) =
                    make_float2(acc[i][j][2], acc[i][j][3]);
            } else {
                bf16 h0, l0, h1, l1;
                __nv_bfloat162 ph, pl;
                split2(acc[i][j][0], h0, l0); split2(acc[i][j][1], h1, l1);
                ph.x = h0; ph.y = h1; pl.x = l0; pl.y = l1;
                *reinterpret_cast<__nv_bfloat162*>(CH + (size_t)r * ldc + col) = ph;
                *reinterpret_cast<__nv_bfloat162*>(CL + (size_t)r * ldc + col) = pl;
                split2(acc[i][j][2], h0, l0); split2(acc[i][j][3], h1, l1);
                ph.x = h0; ph.y = h1; pl.x = l0; pl.y = l1;
                *reinterpret_cast<__nv_bfloat162*>(CH + (size_t)(r + 8) * ldc + col) = ph;
                *reinterpret_cast<__nv_bfloat162*>(CL + (size_t)(r + 8) * ldc + col) = pl;
            }
        }
}

// ---- pass wrappers ----
// P = Xh^T Xh (sel 0) and Q = Xh^T Xl (sel 1); split-K over t in 4 chunks of 512
__global__ void __launch_bounds__(256) k_p1() {
    int z = blockIdx.z;
    int sel = z >> 5, w = z & 31, pair = w >> 2, split = w & 3;
    int b = pair >> 2, q = pair & 3;
    size_t base = ((size_t)b * HID + q * H) * SEQ + split * 512;
    int m0 = blockIdx.x * 128, n0 = blockIdx.y * 128;
    const bf16* A  = g_hidTH + base + (size_t)m0 * SEQ;
    const bf16* Bh = (sel ? g_hidTL : g_hidTH) + base + (size_t)n0 * SEQ;
    float* dst = (sel ? g_Qf : g_Pf) + (size_t)pair * H * H + m0 * H + n0;
    gemm_mma<0, 1>(A, nullptr, SEQ, Bh, nullptr, SEQ, 16, dst, nullptr, nullptr, H);
}
// K = P + Q + Q^T, then split into KH/KL
__global__ void __launch_bounds__(256) k_combK() {
    __shared__ float sh[32][33];
    int pair = blockIdx.z, it = blockIdx.y, jt = blockIdx.x;
    int tx = threadIdx.x & 31, ty = threadIdx.x >> 5;
    const float* P = g_Pf + (size_t)pair * H * H;
    const float* Q = g_Qf + (size_t)pair * H * H;
    #pragma unroll
    for (int i = 0; i < 4; ++i) {
        int r = ty + i * 8;
        sh[r][tx] = Q[(size_t)(jt * 32 + r) * H + it * 32 + tx];
    }
    __syncthreads();
    #pragma unroll
    for (int i = 0; i < 4; ++i) {
        int r = ty + i * 8;
        int row = it * 32 + r, col = jt * 32 + tx;
        size_t idx = (size_t)pair * H * H + (size_t)row * H + col;
        float v = P[(size_t)row * H + col] + Q[(size_t)row * H + col] + sh[tx][r];
        bf16 h, l; split2(v, h, l);
        g_KH[idx] = h; g_KL[idx] = l;
    }
}
__global__ void __launch_bounds__(256) k_p2() {          // tmp = qw * K (K symmetric)
    int z = blockIdx.z, b = z >> 4, a = (z >> 2) & 3, q = z & 3;
    int m0 = blockIdx.x * 128, n0 = blockIdx.y * 128;
    size_t ab = (size_t)a * H * HID + (size_t)m0 * HID + q * H;
    size_t bb = (size_t)((b << 2) | q) * H * H + (size_t)n0 * H;
    size_t cb = (size_t)((b << 2) | a) * H * HID + (size_t)m0 * HID + q * H + n0;
    gemm_mma<2, 3>(g_qH + ab, g_qL + ab, HID, g_KH + bb, g_KL + bb, H,
                   8, nullptr, g_tmpH + cb, g_tmpL + cb, HID);
}
__global__ void __launch_bounds__(256) k_p3() {          // M^T = cT * tmp^T, split-K
    int z = blockIdx.z, pair = z >> 2, split = z & 3;
    int a = pair & 3;
    int m0 = blockIdx.x * 128, n0 = blockIdx.y * 128;
    size_t ab = (size_t)a * H * HID + (size_t)m0 * HID + split * 256;
    size_t bb = (size_t)pair * H * HID + (size_t)n0 * HID + split * 256;
    gemm_mma<0, 3>(g_cTH + ab, g_cTL + ab, HID, g_tmpH + bb, g_tmpL + bb, HID,
                   8, g_Mf + (size_t)pair * H * H + m0 * H + n0, nullptr, nullptr, H);
}
__global__ void __launch_bounds__(256) k_p4(float* __restrict__ out) {  // out = hid * M
    int pair = blockIdx.z, b = pair >> 2, a = pair & 3;
    int m0 = blockIdx.x * 128, n0 = blockIdx.y * 128;
    size_t ab = (size_t)b * SEQ * HID + (size_t)m0 * HID + a * H;
    size_t bb = (size_t)pair * H * H + (size_t)n0 * H;
    gemm_mma<1, 3>(g_hidH + ab, g_hidL + ab, HID, g_MH + bb, g_ML + bb, H,
                   8, out + ab + n0, nullptr, nullptr, HID);
}

// ---- merged prep: hidden split+transpose / queries split / combiners T+split / zero scratch ----
__global__ void __launch_bounds__(256) k_prep(const float* __restrict__ hid,
                                              const float* __restrict__ q,
                                              const float* __restrict__ c) {
    __shared__ bf16 shH[32][33], shL[32][33];
    int blk = blockIdx.x, tid = threadIdx.x;
    if (blk < 4096) {
        int b = blk >> 11, tt = (blk >> 5) & 63, ft = blk & 31;
        int tx = tid & 31, ty = tid >> 5;
        int t0 = tt * 32, f0 = ft * 32;
        #pragma unroll
        for (int i = 0; i < 4; ++i) {
            int r = ty + i * 8;
            size_t idx = ((size_t)b * SEQ + t0 + r) * HID + f0 + tx;
            float v = hid[idx];
            bf16 h, l; split2(v, h, l);
            g_hidH[idx] = h; g_hidL[idx] = l;
            shH[r][tx] = h; shL[r][tx] = l;
        }
        __syncthreads();
        #pragma unroll
        for (int i = 0; i < 4; ++i) {
            int r = ty + i * 8;
            size_t idx = ((size_t)b * HID + f0 + r) * SEQ + t0 + tx;
            g_hidTH[idx] = shH[tx][r];
            g_hidTL[idx] = shL[tx][r];
        }
    } else if (blk < 5120) {
        size_t i = (size_t)(blk - 4096) * 1024 + tid * 4;
        float4 v = *reinterpret_cast<const float4*>(q + i);
        bf16 h, l;
        split2(v.x, h, l); g_qH[i] = h;   g_qL[i] = l;
        split2(v.y, h, l); g_qH[i+1] = h; g_qL[i+1] = l;
        split2(v.z, h, l); g_qH[i+2] = h; g_qL[i+2] = l;
        split2(v.w, h, l); g_qH[i+3] = h; g_qL[i+3] = l;
    } else if (blk < 6144) {
        int z = blk - 5120;
        int a = z >> 8, kt = (z >> 3) & 31, gt = z & 7;
        int tx = tid & 31, ty = tid >> 5;
        int k0 = kt * 32, g0 = gt * 32;
        #pragma unroll
        for (int i = 0; i < 4; ++i) {
            int r = ty + i * 8;
            float v = c[((size_t)a * HID + k0 + r) * H + g0 + tx];
            bf16 h, l; split2(v, h, l);
            shH[r][tx] = h; shL[r][tx] = l;
        }
        __syncthreads();
        #pragma unroll
        for (int i = 0; i < 4; ++i) {
            int r = ty + i * 8;
            size_t idx = ((size_t)a * H + g0 + r) * HID + k0 + tx;
            g_cTH[idx] = shH[tx][r];
            g_cTL[idx] = shL[tx][r];
        }
    } else {
        int z = blk - 6144;                 // 0..383
        int which = z >> 7;
        float* dst = which == 0 ? g_Pf : (which == 1 ? g_Qf : g_Mf);
        size_t base = (size_t)(z & 127) * 4096 + tid * 16;
        float4 zv = make_float4(0.f, 0.f, 0.f, 0.f);
        #pragma unroll
        for (int i = 0; i < 4; ++i)
            *reinterpret_cast<float4*>(dst + base + i * 4) = zv;
    }
}
__global__ void __launch_bounds__(256) k_splitM() {
    size_t i = (size_t)blockIdx.x * 2048 + threadIdx.x * 8;
    #pragma unroll
    for (int j = 0; j < 8; ++j) {
        bf16 h, l; split2(g_Mf[i + j], h, l);
        g_MH[i + j] = h; g_ML[i + j] = l;
    }
}

extern "C" void kernel_launch(void* const* d_in, const int* in_sizes, int n_in,
                              void* d_out, int out_size) {
    const float* hidden    = (const float*)d_in[0];
    const float* queries   = (const float*)d_in[1];
    const float* combiners = (const float*)d_in[2];
    float* out = (float*)d_out;

    cudaFuncSetAttribute(k_p1, cudaFuncAttributeMaxDynamicSharedMemorySize, 49152);
    cudaFuncSetAttribute(k_p2, cudaFuncAttributeMaxDynamicSharedMemorySize, 98304);
    cudaFuncSetAttribute(k_p3, cudaFuncAttributeMaxDynamicSharedMemorySize, 98304);
    cudaFuncSetAttribute(k_p4, cudaFuncAttributeMaxDynamicSharedMemorySize, 98304);

    k_prep<<<6528, 256>>>(hidden, queries, combiners);
    k_p1<<<dim3(2, 2, 64), 256, 49152>>>();
    k_combK<<<dim3(8, 8, 8), 256>>>();
    k_p2<<<dim3(2, 2, 32), 256, 98304>>>();
    k_p3<<<dim3(2, 2, 32), 256, 98304>>>();
    k_splitM<<<256, 256>>>();
    k_p4<<<dim3(16, 2, 8), 256, 98304>>>(out);
}

// round 6
// speedup vs baseline: 2.0715x; 1.0404x over previous
#include <cuda_runtime.h>
#include <cuda_bf16.h>
#include <cstdint>

using bf16 = __nv_bfloat16;

#define BSZ 2
#define SEQ 2048
#define HID 1024
#define NS  4
#define H   256

// ---------------- device scratch ----------------
__device__ __align__(256) bf16 g_hidH [BSZ*SEQ*HID];
__device__ __align__(256) bf16 g_hidL [BSZ*SEQ*HID];
__device__ __align__(256) bf16 g_hidTH[BSZ*HID*SEQ];
__device__ __align__(256) bf16 g_hidTL[BSZ*HID*SEQ];
__device__ __align__(256) bf16 g_qH   [NS*H*HID];
__device__ __align__(256) bf16 g_qL   [NS*H*HID];
__device__ __align__(256) bf16 g_cTH  [NS*H*HID];
__device__ __align__(256) bf16 g_cTL  [NS*H*HID];
__device__ __align__(256) float g_Pf  [8*H*H];      // Xh^T Xh
__device__ __align__(256) float g_Qf  [8*H*H];      // Xh^T Xl
__device__ __align__(256) bf16 g_KH   [8*H*H];
__device__ __align__(256) bf16 g_KL   [8*H*H];
__device__ __align__(256) bf16 g_tmpH [8*H*HID];
__device__ __align__(256) bf16 g_tmpL [8*H*HID];
__device__ __align__(256) float g_Mf  [8*H*H];      // M^T
__device__ __align__(256) bf16 g_MH   [8*H*H];
__device__ __align__(256) bf16 g_ML   [8*H*H];

// ---------------- helpers ----------------
__device__ __forceinline__ void split2(float v, bf16& h, bf16& l) {
    h = __float2bfloat16_rn(v);
    l = __float2bfloat16_rn(v - __bfloat162float(h));
}
__device__ __forceinline__ uint32_t smem_u32(const void* p) {
    uint32_t a;
    asm("{ .reg .u64 t; cvta.to.shared.u64 t, %1; cvt.u32.u64 %0, t; }" : "=r"(a) : "l"(p));
    return a;
}
__device__ __forceinline__ void cpa(uint32_t dst, const void* src) {
    asm volatile("cp.async.ca.shared.global [%0], [%1], 16;" :: "r"(dst), "l"(src));
}
__device__ __forceinline__ void ldsm4(uint32_t (&r)[4], uint32_t addr) {
    asm volatile("ldmatrix.sync.aligned.m8n8.x4.shared.b16 {%0,%1,%2,%3}, [%4];"
        : "=r"(r[0]), "=r"(r[1]), "=r"(r[2]), "=r"(r[3]) : "r"(addr));
}
__device__ __forceinline__ void mma16816(float (&d)[4], const uint32_t (&a)[4],
                                         uint32_t b0, uint32_t b1) {
    asm volatile("mma.sync.aligned.m16n8k16.row.col.f32.bf16.bf16.f32 "
        "{%0,%1,%2,%3}, {%4,%5,%6,%7}, {%8,%9}, {%0,%1,%2,%3};"
        : "+f"(d[0]), "+f"(d[1]), "+f"(d[2]), "+f"(d[3])
        : "r"(a[0]), "r"(a[1]), "r"(a[2]), "r"(a[3]), "r"(b0), "r"(b1));
}
__device__ __forceinline__ uint32_t swz(int row, int c) {
    return (uint32_t)(row * 64 + ((c ^ ((row >> 1) & 3)) << 4));
}

// Stage layout constants
template<int NPROD, int NTILE> struct Lay {
    static constexpr uint32_t AL = 8192u;
    static constexpr uint32_t BH = (NPROD == 3) ? 16384u : 8192u;
    static constexpr uint32_t BN = (NTILE == 128) ? 8192u : 4096u;
    static constexpr uint32_t BL = BH + BN;
    static constexpr uint32_t STAGE = (NPROD == 3) ? (BL + BN) : 16384u;
};

// Load A[128 x 32] (+AL) and B[NTILE x 32] (+BL) into stage sb
template<int NPROD, int NTILE>
__device__ __forceinline__ void load_stage(uint32_t sb,
        const bf16* __restrict__ AH, const bf16* __restrict__ AL, int lda,
        const bf16* __restrict__ BH, const bf16* __restrict__ BL, int ldb, int k0) {
    using L = Lay<NPROD, NTILE>;
    int tid = threadIdx.x;
    #pragma unroll
    for (int t = 0; t < 2; ++t) {
        int cid = tid + t * 256;
        int row = cid >> 2, c = cid & 3;
        uint32_t so = swz(row, c);
        size_t oa = (size_t)row * lda + k0 + c * 8;
        cpa(sb + so, AH + oa);
        if (NPROD == 3) cpa(sb + L::AL + so, AL + oa);
        if (NTILE == 128) {
            size_t ob = (size_t)row * ldb + k0 + c * 8;
            cpa(sb + L::BH + so, BH + ob);
            if (NPROD == 3) cpa(sb + L::BL + so, BL + ob);
        }
    }
    if (NTILE == 64) {
        int row = tid >> 2, c = tid & 3;
        uint32_t so = swz(row, c);
        size_t ob = (size_t)row * ldb + k0 + c * 8;
        cpa(sb + L::BH + so, BH + ob);
        if (NPROD == 3) cpa(sb + L::BL + so, BL + ob);
    }
    asm volatile("cp.async.commit_group;" ::: "memory");
}

// C[128,NTILE] = A[128,K] * B[NTILE,K]^T.  NPROD=3: AhBh+AhBl+AlBh; NPROD=1: AhBh.
// EPI: 0 = atomicAdd fp32, 1 = store fp32, 2 = split-store bf16 H/L
template<int EPI, int NPROD, int NTILE>
__device__ void gemm_mma(const bf16* AH, const bf16* AL, int lda,
                         const bf16* BH, const bf16* BL, int ldb, int kIters,
                         float* Cf, bf16* CH, bf16* CL, int ldc) {
    using L = Lay<NPROD, NTILE>;
    constexpr int MI = (NTILE == 128) ? 4 : 2;
    extern __shared__ char smem[];
    const uint32_t sbase = smem_u32(smem);
    const int tid = threadIdx.x, lane = tid & 31, wid = tid >> 5;
    const int wm = (NTILE == 128) ? (wid & 1) : (wid & 3);
    const int wn = (NTILE == 128) ? (wid >> 1) : (wid >> 2);

    float acc[MI][4][4];
    #pragma unroll
    for (int i = 0; i < MI; ++i)
        #pragma unroll
        for (int j = 0; j < 4; ++j)
            #pragma unroll
            for (int v = 0; v < 4; ++v) acc[i][j][v] = 0.f;

    load_stage<NPROD, NTILE>(sbase,            AH, AL, lda, BH, BL, ldb, 0);
    load_stage<NPROD, NTILE>(sbase + L::STAGE, AH, AL, lda, BH, BL, ldb, 32);

    const int mi = lane >> 3, lr = lane & 7;
    const int rA0 = wm * (MI * 16) + (mi & 1) * 8 + lr;
    const int rB0 = wn * 32 + (mi & 1) * 8 + lr;
    const int chb = mi >> 1;

    for (int it = 0; it < kIters; ++it) {
        if (it + 1 < kIters)
            asm volatile("cp.async.wait_group 1;" ::: "memory");
        else
            asm volatile("cp.async.wait_group 0;" ::: "memory");
        __syncthreads();

        uint32_t sb = sbase + (uint32_t)(it % 3) * L::STAGE;
        if (it + 2 < kIters)
            load_stage<NPROD, NTILE>(sbase + (uint32_t)((it + 2) % 3) * L::STAGE,
                                     AH, AL, lda, BH, BL, ldb, (it + 2) * 32);

        #pragma unroll
        for (int kk = 0; kk < 2; ++kk) {
            int c = kk * 2 + chb;
            uint32_t ah[MI][4], al[MI][4], bh[2][4], bl[2][4];
            #pragma unroll
            for (int i = 0; i < MI; ++i) {
                int r = rA0 + i * 16;
                uint32_t so = swz(r, c);
                ldsm4(ah[i], sb + so);
                if (NPROD == 3) ldsm4(al[i], sb + L::AL + so);
            }
            #pragma unroll
            for (int j = 0; j < 2; ++j) {
                int r = rB0 + j * 16;
                uint32_t so = swz(r, c);
                ldsm4(bh[j], sb + L::BH + so);
                if (NPROD == 3) ldsm4(bl[j], sb + L::BL + so);
            }
            #pragma unroll
            for (int i = 0; i < MI; ++i)
                #pragma unroll
                for (int j = 0; j < 4; ++j) {
                    int j2 = j >> 1, jo = j & 1;
                    mma16816(acc[i][j], ah[i], bh[j2][jo], bh[j2][jo + 2]);
                    if (NPROD == 3) {
                        mma16816(acc[i][j], ah[i], bl[j2][jo], bl[j2][jo + 2]);
                        mma16816(acc[i][j], al[i], bh[j2][jo], bh[j2][jo + 2]);
                    }
                }
        }
    }

    #pragma unroll
    for (int i = 0; i < MI; ++i)
        #pragma unroll
        for (int j = 0; j < 4; ++j) {
            int r   = wm * (MI * 16) + i * 16 + (lane >> 2);
            int col = wn * 32 + j * 8 + (lane & 3) * 2;
            if (EPI == 0) {
                atomicAdd(Cf + (size_t)r * ldc + col,           acc[i][j][0]);
                atomicAdd(Cf + (size_t)r * ldc + col + 1,       acc[i][j][1]);
                atomicAdd(Cf + (size_t)(r + 8) * ldc + col,     acc[i][j][2]);
                atomicAdd(Cf + (size_t)(r + 8) * ldc + col + 1, acc[i][j][3]);
            } else if (EPI == 1) {
                *reinterpret_cast<float2*>(Cf + (size_t)r * ldc + col) =
                    make_float2(acc[i][j][0], acc[i][j][1]);
                *reinterpret_cast<float2*>(Cf + (size_t)(r + 8) * ldc + col) =
                    make_float2(acc[i][j][2], acc[i][j][3]);
            } else {
                bf16 h0, l0, h1, l1;
                __nv_bfloat162 ph, pl;
                split2(acc[i][j][0], h0, l0); split2(acc[i][j][1], h1, l1);
                ph.x = h0; ph.y = h1; pl.x = l0; pl.y = l1;
                *reinterpret_cast<__nv_bfloat162*>(CH + (size_t)r * ldc + col) = ph;
                *reinterpret_cast<__nv_bfloat162*>(CL + (size_t)r * ldc + col) = pl;
                split2(acc[i][j][2], h0, l0); split2(acc[i][j][3], h1, l1);
                ph.x = h0; ph.y = h1; pl.x = l0; pl.y = l1;
                *reinterpret_cast<__nv_bfloat162*>(CH + (size_t)(r + 8) * ldc + col) = ph;
                *reinterpret_cast<__nv_bfloat162*>(CL + (size_t)(r + 8) * ldc + col) = pl;
            }
        }
}

// ---- pass wrappers ----
// P = Xh^T Xh (sel 0), Q = Xh^T Xl (sel 1); split-K over t in 4 chunks of 512
__global__ void __launch_bounds__(256, 2) k_p1() {
    int z = blockIdx.z;
    int sel = z >> 5, w = z & 31, pair = w >> 2, split = w & 3;
    int b = pair >> 2, q = pair & 3;
    size_t base = ((size_t)b * HID + q * H) * SEQ + split * 512;
    int m0 = blockIdx.x * 128, n0 = blockIdx.y * 128;
    const bf16* A  = g_hidTH + base + (size_t)m0 * SEQ;
    const bf16* Bh = (sel ? g_hidTL : g_hidTH) + base + (size_t)n0 * SEQ;
    float* dst = (sel ? g_Qf : g_Pf) + (size_t)pair * H * H + m0 * H + n0;
    gemm_mma<0, 1, 128>(A, nullptr, SEQ, Bh, nullptr, SEQ, 16, dst, nullptr, nullptr, H);
}
// K = P + Q + Q^T, split into KH/KL
__global__ void __launch_bounds__(256) k_combK() {
    __shared__ float sh[32][33];
    int pair = blockIdx.z, it = blockIdx.y, jt = blockIdx.x;
    int tx = threadIdx.x & 31, ty = threadIdx.x >> 5;
    const float* P = g_Pf + (size_t)pair * H * H;
    const float* Q = g_Qf + (size_t)pair * H * H;
    #pragma unroll
    for (int i = 0; i < 4; ++i) {
        int r = ty + i * 8;
        sh[r][tx] = Q[(size_t)(jt * 32 + r) * H + it * 32 + tx];
    }
    __syncthreads();
    #pragma unroll
    for (int i = 0; i < 4; ++i) {
        int r = ty + i * 8;
        int row = it * 32 + r, col = jt * 32 + tx;
        size_t idx = (size_t)pair * H * H + (size_t)row * H + col;
        float v = P[(size_t)row * H + col] + Q[(size_t)row * H + col] + sh[tx][r];
        bf16 h, l; split2(v, h, l);
        g_KH[idx] = h; g_KL[idx] = l;
    }
}
__global__ void __launch_bounds__(256, 2) k_p2() {       // tmp = qw * K (K symmetric)
    int z = blockIdx.z, b = z >> 4, a = (z >> 2) & 3, q = z & 3;
    int m0 = blockIdx.x * 128, n0 = blockIdx.y * 64;
    size_t ab = (size_t)a * H * HID + (size_t)m0 * HID + q * H;
    size_t bb = (size_t)((b << 2) | q) * H * H + (size_t)n0 * H;
    size_t cb = (size_t)((b << 2) | a) * H * HID + (size_t)m0 * HID + q * H + n0;
    gemm_mma<2, 3, 64>(g_qH + ab, g_qL + ab, HID, g_KH + bb, g_KL + bb, H,
                       8, nullptr, g_tmpH + cb, g_tmpL + cb, HID);
}
__global__ void __launch_bounds__(256, 2) k_p3() {       // M^T = cT * tmp^T, split-K 4
    int z = blockIdx.z, pair = z >> 2, split = z & 3;
    int a = pair & 3;
    int m0 = blockIdx.x * 128, n0 = blockIdx.y * 64;
    size_t ab = (size_t)a * H * HID + (size_t)m0 * HID + split * 256;
    size_t bb = (size_t)pair * H * HID + (size_t)n0 * HID + split * 256;
    gemm_mma<0, 3, 64>(g_cTH + ab, g_cTL + ab, HID, g_tmpH + bb, g_tmpL + bb, HID,
                       8, g_Mf + (size_t)pair * H * H + m0 * H + n0, nullptr, nullptr, H);
}
__global__ void __launch_bounds__(256, 2) k_p4(float* __restrict__ out) { // out = hid * M
    int pair = blockIdx.z, b = pair >> 2, a = pair & 3;
    int m0 = blockIdx.x * 128, n0 = blockIdx.y * 64;
    size_t ab = (size_t)b * SEQ * HID + (size_t)m0 * HID + a * H;
    size_t bb = (size_t)pair * H * H + (size_t)n0 * H;
    gemm_mma<1, 3, 64>(g_hidH + ab, g_hidL + ab, HID, g_MH + bb, g_ML + bb, H,
                       8, out + ab + n0, nullptr, nullptr, HID);
}

// ---- merged prep ----
__global__ void __launch_bounds__(256) k_prep(const float* __restrict__ hid,
                                              const float* __restrict__ q,
                                              const float* __restrict__ c) {
    __shared__ bf16 shH[32][33], shL[32][33];
    int blk = blockIdx.x, tid = threadIdx.x;
    if (blk < 4096) {
        int b = blk >> 11, tt = (blk >> 5) & 63, ft = blk & 31;
        int tx = tid & 31, ty = tid >> 5;
        int t0 = tt * 32, f0 = ft * 32;
        #pragma unroll
        for (int i = 0; i < 4; ++i) {
            int r = ty + i * 8;
            size_t idx = ((size_t)b * SEQ + t0 + r) * HID + f0 + tx;
            float v = hid[idx];
            bf16 h, l; split2(v, h, l);
            g_hidH[idx] = h; g_hidL[idx] = l;
            shH[r][tx] = h; shL[r][tx] = l;
        }
        __syncthreads();
        #pragma unroll
        for (int i = 0; i < 4; ++i) {
            int r = ty + i * 8;
            size_t idx = ((size_t)b * HID + f0 + r) * SEQ + t0 + tx;
            g_hidTH[idx] = shH[tx][r];
            g_hidTL[idx] = shL[tx][r];
        }
    } else if (blk < 5120) {
        size_t i = (size_t)(blk - 4096) * 1024 + tid * 4;
        float4 v = *reinterpret_cast<const float4*>(q + i);
        bf16 h, l;
        split2(v.x, h, l); g_qH[i] = h;   g_qL[i] = l;
        split2(v.y, h, l); g_qH[i+1] = h; g_qL[i+1] = l;
        split2(v.z, h, l); g_qH[i+2] = h; g_qL[i+2] = l;
        split2(v.w, h, l); g_qH[i+3] = h; g_qL[i+3] = l;
    } else if (blk < 6144) {
        int z = blk - 5120;
        int a = z >> 8, kt = (z >> 3) & 31, gt = z & 7;
        int tx = tid & 31, ty = tid >> 5;
        int k0 = kt * 32, g0 = gt * 32;
        #pragma unroll
        for (int i = 0; i < 4; ++i) {
            int r = ty + i * 8;
            float v = c[((size_t)a * HID + k0 + r) * H + g0 + tx];
            bf16 h, l; split2(v, h, l);
            shH[r][tx] = h; shL[r][tx] = l;
        }
        __syncthreads();
        #pragma unroll
        for (int i = 0; i < 4; ++i) {
            int r = ty + i * 8;
            size_t idx = ((size_t)a * H + g0 + r) * HID + k0 + tx;
            g_cTH[idx] = shH[tx][r];
            g_cTL[idx] = shL[tx][r];
        }
    } else {
        int z = blk - 6144;                 // 0..383
        int which = z >> 7;
        float* dst = which == 0 ? g_Pf : (which == 1 ? g_Qf : g_Mf);
        size_t base = (size_t)(z & 127) * 4096 + tid * 16;
        float4 zv = make_float4(0.f, 0.f, 0.f, 0.f);
        #pragma unroll
        for (int i = 0; i < 4; ++i)
            *reinterpret_cast<float4*>(dst + base + i * 4) = zv;
    }
}
__global__ void __launch_bounds__(256) k_splitM() {
    size_t i = (size_t)blockIdx.x * 2048 + threadIdx.x * 8;
    #pragma unroll
    for (int j = 0; j < 8; ++j) {
        bf16 h, l; split2(g_Mf[i + j], h, l);
        g_MH[i + j] = h; g_ML[i + j] = l;
    }
}

extern "C" void kernel_launch(void* const* d_in, const int* in_sizes, int n_in,
                              void* d_out, int out_size) {
    const float* hidden    = (const float*)d_in[0];
    const float* queries   = (const float*)d_in[1];
    const float* combiners = (const float*)d_in[2];
    float* out = (float*)d_out;

    cudaFuncSetAttribute(k_p1, cudaFuncAttributeMaxDynamicSharedMemorySize, 49152);
    cudaFuncSetAttribute(k_p2, cudaFuncAttributeMaxDynamicSharedMemorySize, 73728);
    cudaFuncSetAttribute(k_p3, cudaFuncAttributeMaxDynamicSharedMemorySize, 73728);
    cudaFuncSetAttribute(k_p4, cudaFuncAttributeMaxDynamicSharedMemorySize, 73728);

    k_prep<<<6528, 256>>>(hidden, queries, combiners);
    k_p1<<<dim3(2, 2, 64), 256, 49152>>>();
    k_combK<<<dim3(8, 8, 8), 256>>>();
    k_p2<<<dim3(2, 4, 32), 256, 73728>>>();
    k_p3<<<dim3(2, 4, 32), 256, 73728>>>();
    k_splitM<<<256, 256>>>();
    k_p4<<<dim3(16, 4, 8), 256, 73728>>>(out);
}